// round 14
// baseline (speedup 1.0000x reference)
#include <cuda_runtime.h>
#include <cstdint>

#define B_DIM 1024
#define E_DIM 128
#define M_DIM 128
#define N_DIM 512
#define NT    128
#define KT    32

// ---- smem stage layout ----
// A: fragment-packed tf32, 128x32 per k-tile = 4096 u32 = 16KB, no padding
#define A_BYTES 16384
// B: 32 rows x 128 floats, padded ld=136 -> (136k+n)%32=(8k+n)%32 conflict-free
#define B_LD 136
#define B_BYTES (KT * B_LD * 4)            // 17408
#define STAGE_BYTES (A_BYTES + B_BYTES)    // 33792
#define NSTAGE 3
#define SMEM_TOTAL (STAGE_BYTES * NSTAGE)  // 101376

// W pre-packed as tf32 fragments: [kt(8)][ks(4)][mt'(8)][lane(32)][j(4)]
__device__ uint32_t g_Wpack[8 * 4 * 8 * 32 * 4];
__device__ float    g_bias[M_DIM];

static __device__ __forceinline__ uint32_t sm_u32(const void* p) {
    uint32_t a;
    asm("{ .reg .u64 t; cvta.to.shared.u64 t, %1; cvt.u32.u64 %0, t; }" : "=r"(a) : "l"(p));
    return a;
}

#define CP_ASYNC16(dst, src) \
    asm volatile("cp.async.cg.shared.global [%0], [%1], 16;" :: "r"(dst), "l"(src) : "memory")
#define CP_COMMIT() asm volatile("cp.async.commit_group;" ::: "memory")
#define CP_WAIT1()  asm volatile("cp.async.wait_group 1;" ::: "memory")

static __device__ __forceinline__ uint32_t f2tf(float x) {
    uint32_t r;
    asm("cvt.rna.tf32.f32 %0, %1;" : "=r"(r) : "f"(x));
    return r;
}

static __device__ __forceinline__ void mma8(float* c, const uint32_t* a, uint32_t b0, uint32_t b1) {
    asm volatile(
        "mma.sync.aligned.m16n8k8.row.col.f32.tf32.tf32.f32 "
        "{%0,%1,%2,%3}, {%4,%5,%6,%7}, {%8,%9}, {%0,%1,%2,%3};"
        : "+f"(c[0]), "+f"(c[1]), "+f"(c[2]), "+f"(c[3])
        : "r"(a[0]), "r"(a[1]), "r"(a[2]), "r"(a[3]), "r"(b0), "r"(b1));
}

// Prologue: pack W=[W_e|W_h] (M=128 x K=256) into per-lane fragment order + bias sum.
__global__ void __launch_bounds__(256) pack_kernel(
    const float* __restrict__ W_e, const float* __restrict__ b_e,
    const float* __restrict__ W_h, const float* __restrict__ b_h)
{
    int f = blockIdx.x * 256 + threadIdx.x;            // 0 .. 32767
    int j   = f & 3;
    int lid = (f >> 2) & 31;
    int mt  = (f >> 7) & 7;
    int ks  = (f >> 10) & 3;
    int kt  = (f >> 12) & 7;
    int m = mt * 16 + (lid >> 2) + ((j & 1) ? 8 : 0);
    int k = kt * 32 + ks * 8 + (lid & 3) + ((j >> 1) ? 4 : 0);
    float v = (k < 128) ? W_e[m * 128 + k] : W_h[m * 128 + (k - 128)];
    g_Wpack[f] = f2tf(v);
    if (f < M_DIM) g_bias[f] = b_e[f] + b_h[f];
}

__global__ void __launch_bounds__(256, 2) msg_kernel(
    const float* __restrict__ h_w, const float* __restrict__ e_vw,
    float* __restrict__ out)
{
    extern __shared__ float smem[];
    const uint32_t sbase = sm_u32(smem);
    const int tid = threadIdx.x;
    const int wid = tid >> 5, lid = tid & 31;
    const int warp_m = wid & 1;        // 2 warps over M (64 rows each)
    const int warp_n = wid >> 1;       // 4 warps over N (32 cols each)
    const int lidq = lid >> 2, lidr = lid & 3;
    const int n0 = blockIdx.x * NT;
    const int b  = blockIdx.y;

    auto issue_tile = [&](int kt, int stage) {
        const uint32_t abase = sbase + stage * STAGE_BYTES;
        const uint32_t bbase = abase + A_BYTES;
        // A: packed, linear — 1024 x 16B chunks
        const uint32_t* Apack = g_Wpack + (size_t)kt * 4096;
#pragma unroll
        for (int i = 0; i < 4; i++) {
            int c = tid + 256 * i;
            CP_ASYNC16(abase + (uint32_t)c * 16, Apack + (size_t)c * 4);
        }
        // B: 32 rows x 128 floats (row stride 512 floats) = 1024 x 16B chunks
        const float* Bsrc = (kt < 4)
            ? (e_vw + ((size_t)b * E_DIM + (size_t)kt * KT) * N_DIM + n0)
            : (h_w  + ((size_t)b * E_DIM + (size_t)(kt - 4) * KT) * N_DIM + n0);
#pragma unroll
        for (int i = 0; i < 4; i++) {
            int cid = tid + 256 * i;
            int kr = cid >> 5, c = cid & 31;
            CP_ASYNC16(bbase + (uint32_t)kr * (B_LD * 4) + (uint32_t)c * 16,
                       Bsrc + (size_t)kr * N_DIM + c * 4);
        }
        CP_COMMIT();
    };

    float acc[4][4][4];
#pragma unroll
    for (int i = 0; i < 4; i++)
#pragma unroll
        for (int j = 0; j < 4; j++)
#pragma unroll
            for (int k = 0; k < 4; k++) acc[i][j][k] = 0.0f;

    issue_tile(0, 0);
    issue_tile(1, 1);

#pragma unroll 1
    for (int kt = 0; kt < 8; kt++) {
        CP_WAIT1();
        __syncthreads();
        if (kt + 2 < 8) issue_tile(kt + 2, (kt + 2) % NSTAGE);
        else            CP_COMMIT();   // keep group accounting aligned

        const uint32_t astage = sbase + (uint32_t)(kt % NSTAGE) * STAGE_BYTES;
        const float* sB = smem + (size_t)(kt % NSTAGE) * (STAGE_BYTES / 4) + A_BYTES / 4;

#pragma unroll
        for (int ksi = 0; ksi < 4; ksi++) {
            // per-warp rotated ks order: decorrelates post-barrier LDS bursts
            // across warps (accumulation order-independent)
            const int ks = (ksi + wid) & 3;
            const int k0 = ks * 8 + lidr;

            uint32_t bf0[4], bf1[4];
#pragma unroll
            for (int nt = 0; nt < 4; nt++) {
                const int nn = warp_n * 32 + nt * 8 + lidq;
                bf0[nt] = f2tf(sB[(size_t)k0 * B_LD + nn]);
                bf1[nt] = f2tf(sB[(size_t)(k0 + 4) * B_LD + nn]);
            }

            // mt-granular interleave: load af[mt+1] while issuing mt's MMAs
            uint32_t af[2][4];
            {
                uint32_t addr = astage +
                    (uint32_t)(((ks * 8) + (warp_m * 4 + 0)) * 32 + lid) * 16;
                asm volatile("ld.shared.v4.b32 {%0,%1,%2,%3}, [%4];"
                             : "=r"(af[0][0]), "=r"(af[0][1]),
                               "=r"(af[0][2]), "=r"(af[0][3]) : "r"(addr));
            }
#pragma unroll
            for (int mt = 0; mt < 4; mt++) {
                if (mt < 3) {
                    uint32_t addr = astage +
                        (uint32_t)(((ks * 8) + (warp_m * 4 + mt + 1)) * 32 + lid) * 16;
                    asm volatile("ld.shared.v4.b32 {%0,%1,%2,%3}, [%4];"
                                 : "=r"(af[(mt + 1) & 1][0]), "=r"(af[(mt + 1) & 1][1]),
                                   "=r"(af[(mt + 1) & 1][2]), "=r"(af[(mt + 1) & 1][3])
                                 : "r"(addr));
                }
#pragma unroll
                for (int nt = 0; nt < 4; nt++)
                    mma8(acc[mt][nt], af[mt & 1], bf0[nt], bf1[nt]);
            }
        }
    }

    // ---------- epilogue: bias + store ----------
#pragma unroll
    for (int mt = 0; mt < 4; mt++) {
        const int r0 = warp_m * 64 + mt * 16 + lidq;
        const float bias0 = g_bias[r0];
        const float bias1 = g_bias[r0 + 8];
        float* orow0 = out + ((size_t)b * M_DIM + r0) * N_DIM + n0;
        float* orow1 = out + ((size_t)b * M_DIM + r0 + 8) * N_DIM + n0;
#pragma unroll
        for (int nt = 0; nt < 4; nt++) {
            const int col = warp_n * 32 + nt * 8 + 2 * lidr;
            float2 v0, v1;
            v0.x = acc[mt][nt][0] + bias0; v0.y = acc[mt][nt][1] + bias0;
            v1.x = acc[mt][nt][2] + bias1; v1.y = acc[mt][nt][3] + bias1;
            *reinterpret_cast<float2*>(orow0 + col) = v0;
            *reinterpret_cast<float2*>(orow1 + col) = v1;
        }
    }
}

extern "C" void kernel_launch(void* const* d_in, const int* in_sizes, int n_in,
                              void* d_out, int out_size) {
    // metadata order: h_v (unused), h_w, e_vw, W_e, b_e, W_h, b_h
    const float* h_w  = (const float*)d_in[1];
    const float* e_vw = (const float*)d_in[2];
    const float* W_e  = (const float*)d_in[3];
    const float* b_e  = (const float*)d_in[4];
    const float* W_h  = (const float*)d_in[5];
    const float* b_h  = (const float*)d_in[6];
    float* out = (float*)d_out;

    pack_kernel<<<128, 256>>>(W_e, b_e, W_h, b_h);

    cudaFuncSetAttribute(msg_kernel, cudaFuncAttributeMaxDynamicSharedMemorySize, SMEM_TOTAL);
    dim3 grid(N_DIM / NT, B_DIM);
    msg_kernel<<<grid, 256, SMEM_TOTAL>>>(h_w, e_vw, out);
}

// round 15
// speedup vs baseline: 1.6060x; 1.6060x over previous
#include <cuda_runtime.h>
#include <cstdint>

#define B_DIM 1024
#define E_DIM 128
#define M_DIM 128
#define N_DIM 512
#define NT    128
#define KT    32

// ---- smem stage layout ----
// A: fragment-packed tf32, 128x32 per k-tile = 4096 u32 = 16KB, no padding
#define A_BYTES 16384
// B: 32 rows x 128 floats, padded ld=136 -> (136k+n)%32=(8k+n)%32 conflict-free
#define B_LD 136
#define B_BYTES (KT * B_LD * 4)            // 17408
#define STAGE_BYTES (A_BYTES + B_BYTES)    // 33792
#define NSTAGE 3
#define SMEM_TOTAL (STAGE_BYTES * NSTAGE)  // 101376

// W pre-packed as tf32 fragments: [kt(8)][ks(4)][mt'(8)][lane(32)][j(4)]
__device__ uint32_t g_Wpack[8 * 4 * 8 * 32 * 4];
__device__ float    g_bias[M_DIM];

static __device__ __forceinline__ uint32_t sm_u32(const void* p) {
    uint32_t a;
    asm("{ .reg .u64 t; cvta.to.shared.u64 t, %1; cvt.u32.u64 %0, t; }" : "=r"(a) : "l"(p));
    return a;
}

#define CP_ASYNC16(dst, src) \
    asm volatile("cp.async.cg.shared.global [%0], [%1], 16;" :: "r"(dst), "l"(src) : "memory")
#define CP_COMMIT() asm volatile("cp.async.commit_group;" ::: "memory")
#define CP_WAIT1()  asm volatile("cp.async.wait_group 1;" ::: "memory")

static __device__ __forceinline__ uint32_t f2tf(float x) {
    uint32_t r;
    asm("cvt.rna.tf32.f32 %0, %1;" : "=r"(r) : "f"(x));
    return r;
}

static __device__ __forceinline__ void mma8(float* c, const uint32_t* a, uint32_t b0, uint32_t b1) {
    asm volatile(
        "mma.sync.aligned.m16n8k8.row.col.f32.tf32.tf32.f32 "
        "{%0,%1,%2,%3}, {%4,%5,%6,%7}, {%8,%9}, {%0,%1,%2,%3};"
        : "+f"(c[0]), "+f"(c[1]), "+f"(c[2]), "+f"(c[3])
        : "r"(a[0]), "r"(a[1]), "r"(a[2]), "r"(a[3]), "r"(b0), "r"(b1));
}

// Prologue: pack W=[W_e|W_h] (M=128 x K=256) into per-lane fragment order + bias sum.
__global__ void __launch_bounds__(256) pack_kernel(
    const float* __restrict__ W_e, const float* __restrict__ b_e,
    const float* __restrict__ W_h, const float* __restrict__ b_h)
{
    int f = blockIdx.x * 256 + threadIdx.x;            // 0 .. 32767
    int j   = f & 3;
    int lid = (f >> 2) & 31;
    int mt  = (f >> 7) & 7;
    int ks  = (f >> 10) & 3;
    int kt  = (f >> 12) & 7;
    int m = mt * 16 + (lid >> 2) + ((j & 1) ? 8 : 0);
    int k = kt * 32 + ks * 8 + (lid & 3) + ((j >> 1) ? 4 : 0);
    float v = (k < 128) ? W_e[m * 128 + k] : W_h[m * 128 + (k - 128)];
    g_Wpack[f] = f2tf(v);
    if (f < M_DIM) g_bias[f] = b_e[f] + b_h[f];
}

__global__ void __launch_bounds__(128, 2) msg_kernel(
    const float* __restrict__ h_w, const float* __restrict__ e_vw,
    float* __restrict__ out)
{
    extern __shared__ float smem[];
    const uint32_t sbase = sm_u32(smem);
    const int tid = threadIdx.x;
    const int wid = tid >> 5, lid = tid & 31;
    const int warp_m = wid & 1;        // 2 warps over M (64 rows each)
    const int warp_n = wid >> 1;       // 2 warps over N (64 cols each)
    const int lidq = lid >> 2, lidr = lid & 3;
    const int n0 = blockIdx.x * NT;
    const int b  = blockIdx.y;

    auto issue_tile = [&](int kt, int stage) {
        const uint32_t abase = sbase + stage * STAGE_BYTES;
        const uint32_t bbase = abase + A_BYTES;
        // A: packed, linear — 1024 x 16B chunks (8 per thread)
        const uint32_t* Apack = g_Wpack + (size_t)kt * 4096;
#pragma unroll
        for (int i = 0; i < 8; i++) {
            int c = tid + 128 * i;
            CP_ASYNC16(abase + (uint32_t)c * 16, Apack + (size_t)c * 4);
        }
        // B: 32 rows x 128 floats (row stride 512 floats) = 1024 x 16B chunks
        const float* Bsrc = (kt < 4)
            ? (e_vw + ((size_t)b * E_DIM + (size_t)kt * KT) * N_DIM + n0)
            : (h_w  + ((size_t)b * E_DIM + (size_t)(kt - 4) * KT) * N_DIM + n0);
#pragma unroll
        for (int i = 0; i < 8; i++) {
            int cid = tid + 128 * i;
            int kr = cid >> 5, c = cid & 31;
            CP_ASYNC16(bbase + (uint32_t)kr * (B_LD * 4) + (uint32_t)c * 16,
                       Bsrc + (size_t)kr * N_DIM + c * 4);
        }
        CP_COMMIT();
    };

    // 64x64 warp tile: acc[mt(4)][nt(8)][4] = 128 regs
    float acc[4][8][4];
#pragma unroll
    for (int i = 0; i < 4; i++)
#pragma unroll
        for (int j = 0; j < 8; j++)
#pragma unroll
            for (int k = 0; k < 4; k++) acc[i][j][k] = 0.0f;

    issue_tile(0, 0);
    issue_tile(1, 1);

#pragma unroll 1
    for (int kt = 0; kt < 8; kt++) {
        CP_WAIT1();
        __syncthreads();
        if (kt + 2 < 8) issue_tile(kt + 2, (kt + 2) % NSTAGE);
        else            CP_COMMIT();   // keep group accounting aligned

        const uint32_t astage = sbase + (uint32_t)(kt % NSTAGE) * STAGE_BYTES;
        const float* sB = smem + (size_t)(kt % NSTAGE) * (STAGE_BYTES / 4) + A_BYTES / 4;

#pragma unroll
        for (int ks = 0; ks < 4; ks++) {
            const int k0 = ks * 8 + lidr;
            uint32_t af[4][4], bf0[8], bf1[8];
#pragma unroll
            for (int mt = 0; mt < 4; mt++) {
                uint32_t addr = astage +
                    (uint32_t)(((ks * 8) + (warp_m * 4 + mt)) * 32 + lid) * 16;
                asm volatile("ld.shared.v4.b32 {%0,%1,%2,%3}, [%4];"
                             : "=r"(af[mt][0]), "=r"(af[mt][1]),
                               "=r"(af[mt][2]), "=r"(af[mt][3])
                             : "r"(addr));
            }
#pragma unroll
            for (int nt = 0; nt < 8; nt++) {
                const int nn = warp_n * 64 + nt * 8 + lidq;
                bf0[nt] = f2tf(sB[(size_t)k0 * B_LD + nn]);
                bf1[nt] = f2tf(sB[(size_t)(k0 + 4) * B_LD + nn]);
            }
#pragma unroll
            for (int mt = 0; mt < 4; mt++)
#pragma unroll
                for (int nt = 0; nt < 8; nt++)
                    mma8(acc[mt][nt], af[mt], bf0[nt], bf1[nt]);
        }
    }

    // ---------- epilogue: bias + store ----------
#pragma unroll
    for (int mt = 0; mt < 4; mt++) {
        const int r0 = warp_m * 64 + mt * 16 + lidq;
        const float bias0 = g_bias[r0];
        const float bias1 = g_bias[r0 + 8];
        float* orow0 = out + ((size_t)b * M_DIM + r0) * N_DIM + n0;
        float* orow1 = out + ((size_t)b * M_DIM + r0 + 8) * N_DIM + n0;
#pragma unroll
        for (int nt = 0; nt < 8; nt++) {
            const int col = warp_n * 64 + nt * 8 + 2 * lidr;
            float2 v0, v1;
            v0.x = acc[mt][nt][0] + bias0; v0.y = acc[mt][nt][1] + bias0;
            v1.x = acc[mt][nt][2] + bias1; v1.y = acc[mt][nt][3] + bias1;
            *reinterpret_cast<float2*>(orow0 + col) = v0;
            *reinterpret_cast<float2*>(orow1 + col) = v1;
        }
    }
}

extern "C" void kernel_launch(void* const* d_in, const int* in_sizes, int n_in,
                              void* d_out, int out_size) {
    // metadata order: h_v (unused), h_w, e_vw, W_e, b_e, W_h, b_h
    const float* h_w  = (const float*)d_in[1];
    const float* e_vw = (const float*)d_in[2];
    const float* W_e  = (const float*)d_in[3];
    const float* b_e  = (const float*)d_in[4];
    const float* W_h  = (const float*)d_in[5];
    const float* b_h  = (const float*)d_in[6];
    float* out = (float*)d_out;

    pack_kernel<<<128, 256>>>(W_e, b_e, W_h, b_h);

    cudaFuncSetAttribute(msg_kernel, cudaFuncAttributeMaxDynamicSharedMemorySize, SMEM_TOTAL);
    dim3 grid(N_DIM / NT, B_DIM);
    msg_kernel<<<grid, 128, SMEM_TOTAL>>>(h_w, e_vw, out);
}